// round 2
// baseline (speedup 1.0000x reference)
#include <cuda_runtime.h>

// ---------------- scratch (static device globals; no allocations) ----------
__device__ float g_cA[96 * 256 * 256];          // 25 MB
__device__ float g_t1[96 * 16 * 128 * 128];     // 100 MB

// ---------------- Kernel A: Haar DWT ---------------------------------------
// x: [96, 512, 512] (flattened [32,3,...]); writes cA to scratch,
// cH/cV directly into d_out high region (layout: img*2n + idx / +n).
__global__ void dwt_kernel(const float* __restrict__ x, float* __restrict__ out_high) {
    int img = blockIdx.y;
    int pix = blockIdx.x * 256 + threadIdx.x;     // 0..65535
    int oy = pix >> 8, ox = pix & 255;
    const float* base = x + (size_t)img * 262144 + (size_t)(2 * oy) * 512 + 2 * ox;
    float2 t = *(const float2*)base;
    float2 bo = *(const float2*)(base + 512);
    float a = t.x, b = t.y, c = bo.x, d = bo.y;
    float cA = (a + b + c + d) * 0.5f;
    float cH = (a + b - c - d) * 0.5f;
    float cV = (a - b + c - d) * 0.5f;
    g_cA[img * 65536 + pix] = cA;
    float* hb = out_high + (size_t)img * 131072;
    hb[pix] = cH;
    hb[65536 + pix] = cV;
}

// ---------------- Kernel B: conv1 (1->16, 3x3 SAME) + relu + maxpool2 -------
// grid (4,4,96), block (32,32). Each thread: one pooled pixel, all 16 channels.
__global__ void conv1_kernel(const float* __restrict__ w1, const float* __restrict__ b1) {
    __shared__ float sIn[66][68];
    __shared__ float sW[144];
    __shared__ float sB[16];
    int img = blockIdx.z;
    int bx0 = blockIdx.x * 64, by0 = blockIdx.y * 64;   // conv-region origin (256x256)
    int tid = threadIdx.y * 32 + threadIdx.x;
    if (tid < 144) sW[tid] = w1[tid];
    if (tid < 16) sB[tid] = b1[tid];
    const float* in = g_cA + (size_t)img * 65536;
    for (int idx = tid; idx < 66 * 66; idx += 1024) {
        int r = idx / 66, c = idx % 66;
        int gy = by0 - 1 + r, gx = bx0 - 1 + c;
        float v = 0.f;
        if ((unsigned)gy < 256u && (unsigned)gx < 256u) v = in[gy * 256 + gx];
        sIn[r][c] = v;
    }
    __syncthreads();

    int ly = 2 * threadIdx.y, lx = 2 * threadIdx.x;
    float p[4][4];
#pragma unroll
    for (int r = 0; r < 4; r++)
#pragma unroll
        for (int c = 0; c < 4; c++) p[r][c] = sIn[ly + r][lx + c];

    int py = blockIdx.y * 32 + threadIdx.y;
    int px = blockIdx.x * 32 + threadIdx.x;
    float* outp = g_t1 + (size_t)img * 16 * 16384 + py * 128 + px;
#pragma unroll
    for (int oc = 0; oc < 16; oc++) {
        float bb = sB[oc];
        float s00 = bb, s01 = bb, s10 = bb, s11 = bb;
#pragma unroll
        for (int ky = 0; ky < 3; ky++)
#pragma unroll
            for (int kx = 0; kx < 3; kx++) {
                float w = sW[oc * 9 + ky * 3 + kx];
                s00 += p[ky][kx] * w;
                s01 += p[ky][kx + 1] * w;
                s10 += p[ky + 1][kx] * w;
                s11 += p[ky + 1][kx + 1] * w;
            }
        float m = fmaxf(fmaxf(s00, s01), fmaxf(s10, s11));
        outp[oc * 16384] = fmaxf(m, 0.f);
    }
}

// ---------------- Kernel C: conv2 (16->8, 3x3) + relu + pool + conv3 (8->4, 1x1)
// grid (4,4,96), block (16,16). Dynamic smem: 16ch x 34x35 halo tile + weights.
__global__ void conv23_kernel(const float* __restrict__ w2, const float* __restrict__ b2,
                              const float* __restrict__ w3, const float* __restrict__ b3,
                              float* __restrict__ out_low) {
    extern __shared__ float sm[];
    float* ins = sm;                 // 16 * 34 * 35 = 19040
    float* w2s = sm + 19040;         // 1152
    float* b2s = w2s + 1152;         // 8
    float* w3s = b2s + 8;            // 32
    float* b3s = w3s + 32;           // 4

    int img = blockIdx.z;
    int bx0 = blockIdx.x * 32, by0 = blockIdx.y * 32;   // conv2-region origin (128x128)
    int tid = threadIdx.y * 16 + threadIdx.x;           // 256 threads

    for (int i = tid; i < 1152; i += 256) w2s[i] = w2[i];
    if (tid < 8) b2s[tid] = b2[tid];
    if (tid < 32) w3s[tid] = w3[tid];
    if (tid < 4) b3s[tid] = b3[tid];

    const float* t1b = g_t1 + (size_t)img * 16 * 16384;
    for (int idx = tid; idx < 16 * 34 * 34; idx += 256) {
        int ic = idx / 1156;
        int rem = idx - ic * 1156;
        int r = rem / 34, c = rem - r * 34;
        int gy = by0 - 1 + r, gx = bx0 - 1 + c;
        float v = 0.f;
        if ((unsigned)gy < 128u && (unsigned)gx < 128u) v = t1b[ic * 16384 + gy * 128 + gx];
        ins[ic * 1190 + r * 35 + c] = v;
    }
    __syncthreads();

    int ly = 2 * threadIdx.y, lx = 2 * threadIdx.x;
    float acc[8][4];
#pragma unroll
    for (int oc = 0; oc < 8; oc++) {
        float bb = b2s[oc];
        acc[oc][0] = bb; acc[oc][1] = bb; acc[oc][2] = bb; acc[oc][3] = bb;
    }

#pragma unroll 1
    for (int ic = 0; ic < 16; ic++) {
        float p[4][4];
        const float* ip = ins + ic * 1190 + ly * 35 + lx;
#pragma unroll
        for (int r = 0; r < 4; r++)
#pragma unroll
            for (int c = 0; c < 4; c++) p[r][c] = ip[r * 35 + c];
#pragma unroll
        for (int oc = 0; oc < 8; oc++) {
            const float* wp = w2s + (oc * 16 + ic) * 9;
#pragma unroll
            for (int ky = 0; ky < 3; ky++)
#pragma unroll
                for (int kx = 0; kx < 3; kx++) {
                    float w = wp[ky * 3 + kx];
                    acc[oc][0] += p[ky][kx] * w;
                    acc[oc][1] += p[ky][kx + 1] * w;
                    acc[oc][2] += p[ky + 1][kx] * w;
                    acc[oc][3] += p[ky + 1][kx + 1] * w;
                }
        }
    }

    float v8[8];
#pragma unroll
    for (int oc = 0; oc < 8; oc++) {
        float m = fmaxf(fmaxf(acc[oc][0], acc[oc][1]), fmaxf(acc[oc][2], acc[oc][3]));
        v8[oc] = fmaxf(m, 0.f);
    }

    int oy = (by0 >> 1) + threadIdx.y;
    int ox = (bx0 >> 1) + threadIdx.x;
    float* ob = out_low + (size_t)img * 4 * 4096 + oy * 64 + ox;
#pragma unroll
    for (int o3 = 0; o3 < 4; o3++) {
        float s = b3s[o3];
#pragma unroll
        for (int ic = 0; ic < 8; ic++) s += v8[ic] * w3s[o3 * 8 + ic];
        ob[o3 * 4096] = s;
    }
}

// ---------------------------------------------------------------------------
extern "C" void kernel_launch(void* const* d_in, const int* in_sizes, int n_in,
                              void* d_out, int out_size) {
    const float* x  = (const float*)d_in[0];
    const float* w1 = (const float*)d_in[1];
    const float* b1 = (const float*)d_in[2];
    const float* w2 = (const float*)d_in[3];
    const float* b2 = (const float*)d_in[4];
    const float* w3 = (const float*)d_in[5];
    const float* b3 = (const float*)d_in[6];
    float* out = (float*)d_out;

    const int LOW_SIZE = 96 * 4 * 64 * 64;          // 1,572,864
    const int SMEM_C = (19040 + 1152 + 8 + 32 + 4) * 4;  // 80,944 bytes

    cudaFuncSetAttribute(conv23_kernel, cudaFuncAttributeMaxDynamicSharedMemorySize, SMEM_C);

    dwt_kernel<<<dim3(256, 96), 256>>>(x, out + LOW_SIZE);
    conv1_kernel<<<dim3(4, 4, 96), dim3(32, 32)>>>(w1, b1);
    conv23_kernel<<<dim3(4, 4, 96), dim3(16, 16), SMEM_C>>>(w2, b2, w3, b3, out);
}

// round 3
// speedup vs baseline: 1.1583x; 1.1583x over previous
#include <cuda_runtime.h>

typedef unsigned long long ull;

// ---------------- packed f32x2 helpers (Blackwell FFMA2 path) ---------------
__device__ __forceinline__ ull pack2(float lo, float hi) {
    ull r; asm("mov.b64 %0, {%1, %2};" : "=l"(r) : "f"(lo), "f"(hi)); return r;
}
__device__ __forceinline__ ull dup2(float v) {
    ull r; asm("mov.b64 %0, {%1, %1};" : "=l"(r) : "f"(v)); return r;
}
__device__ __forceinline__ void unpack2(ull v, float& lo, float& hi) {
    asm("mov.b64 {%0, %1}, %2;" : "=f"(lo), "=f"(hi) : "l"(v));
}
__device__ __forceinline__ ull fma2(ull a, ull b, ull c) {
    ull d; asm("fma.rn.f32x2 %0, %1, %2, %3;" : "=l"(d) : "l"(a), "l"(b), "l"(c)); return d;
}

// ---------------- scratch (static device globals; no allocations) ----------
__device__ float g_cA[96 * 256 * 256];          // 25 MB
__device__ float g_t1[96 * 16 * 128 * 128];     // 100 MB

// ---------------- Kernel A: Haar DWT (float4 loads, 2 px / thread) ---------
__global__ void dwt_kernel(const float* __restrict__ x, float* __restrict__ out_high) {
    int img = blockIdx.y;
    int t = blockIdx.x * 256 + threadIdx.x;       // 0..32767
    int oy = t >> 7;
    int oxp = (t & 127) << 1;                     // even output col
    const float* base = x + (size_t)img * 262144 + (size_t)oy * 1024 + 2 * oxp;
    float4 tp = *(const float4*)base;
    float4 bt = *(const float4*)(base + 512);
    float cA0 = (tp.x + tp.y + bt.x + bt.y) * 0.5f;
    float cH0 = (tp.x + tp.y - bt.x - bt.y) * 0.5f;
    float cV0 = (tp.x - tp.y + bt.x - bt.y) * 0.5f;
    float cA1 = (tp.z + tp.w + bt.z + bt.w) * 0.5f;
    float cH1 = (tp.z + tp.w - bt.z - bt.w) * 0.5f;
    float cV1 = (tp.z - tp.w + bt.z - bt.w) * 0.5f;
    int o = oy * 256 + oxp;
    *(float2*)(g_cA + (size_t)img * 65536 + o) = make_float2(cA0, cA1);
    float* hb = out_high + (size_t)img * 131072;
    *(float2*)(hb + o) = make_float2(cH0, cH1);
    *(float2*)(hb + 65536 + o) = make_float2(cV0, cV1);
}

// ---------------- Kernel B: conv1 (1->16) + relu + pool, FFMA2 over oc-pairs
// grid (8,8,96), block (16,16). Tile: 32x32 conv region -> 16x16 pooled.
__global__ void conv1_kernel(const float* __restrict__ w1, const float* __restrict__ b1) {
    __shared__ float sIn[34 * 36];
    __shared__ ull   sW[72];        // (oc-pair, k): (w[2op][k], w[2op+1][k])
    __shared__ float sB[16];
    int img = blockIdx.z;
    int bx0 = blockIdx.x * 32, by0 = blockIdx.y * 32;   // conv origin in 256x256
    int tid = threadIdx.y * 16 + threadIdx.x;            // 256 threads

    if (tid < 72) {
        int op = tid / 9, k = tid - op * 9;
        sW[tid] = pack2(w1[(2 * op) * 9 + k], w1[(2 * op + 1) * 9 + k]);
    }
    if (tid < 16) sB[tid] = b1[tid];

    const float* in = g_cA + (size_t)img * 65536;
    for (int idx = tid; idx < 34 * 34; idx += 256) {
        int r = idx / 34, c = idx - r * 34;
        int gy = by0 - 1 + r, gx = bx0 - 1 + c;
        float v = 0.f;
        if ((unsigned)gy < 256u && (unsigned)gx < 256u) v = in[gy * 256 + gx];
        sIn[r * 36 + c] = v;
    }
    __syncthreads();

    int ly = 2 * threadIdx.y, lx = 2 * threadIdx.x;
    const float* ip = sIn + ly * 36 + lx;
    float p[4][4];
#pragma unroll
    for (int r = 0; r < 4; r++) {
        float2 u0 = *(const float2*)(ip + r * 36);
        float2 u1 = *(const float2*)(ip + r * 36 + 2);
        p[r][0] = u0.x; p[r][1] = u0.y; p[r][2] = u1.x; p[r][3] = u1.y;
    }
    ull pd[4][4];
#pragma unroll
    for (int r = 0; r < 4; r++)
#pragma unroll
        for (int c = 0; c < 4; c++) pd[r][c] = dup2(p[r][c]);

    int py = blockIdx.y * 16 + threadIdx.y;
    int px = blockIdx.x * 16 + threadIdx.x;
    float* outp = g_t1 + (size_t)img * 16 * 16384 + py * 128 + px;

#pragma unroll
    for (int op = 0; op < 8; op++) {
        ull bb = pack2(sB[2 * op], sB[2 * op + 1]);
        ull a0 = bb, a1 = bb, a2 = bb, a3 = bb;
        const ull* wp = sW + op * 9;
#pragma unroll
        for (int ky = 0; ky < 3; ky++)
#pragma unroll
            for (int kx = 0; kx < 3; kx++) {
                ull w = wp[ky * 3 + kx];
                a0 = fma2(pd[ky][kx],         w, a0);
                a1 = fma2(pd[ky][kx + 1],     w, a1);
                a2 = fma2(pd[ky + 1][kx],     w, a2);
                a3 = fma2(pd[ky + 1][kx + 1], w, a3);
            }
        float s0l, s0h, s1l, s1h, s2l, s2h, s3l, s3h;
        unpack2(a0, s0l, s0h); unpack2(a1, s1l, s1h);
        unpack2(a2, s2l, s2h); unpack2(a3, s3l, s3h);
        float ml = fmaxf(fmaxf(s0l, s1l), fmaxf(s2l, s3l));
        float mh = fmaxf(fmaxf(s0h, s1h), fmaxf(s2h, s3h));
        outp[(2 * op) * 16384]     = fmaxf(ml, 0.f);
        outp[(2 * op + 1) * 16384] = fmaxf(mh, 0.f);
    }
}

// ---------------- Kernel C: conv2 (16->8) + relu + pool + conv3 (8->4) -----
// grid (4,4,96), block (16,16). FFMA2 over oc-pairs.
__global__ void conv23_kernel(const float* __restrict__ w2, const float* __restrict__ b2,
                              const float* __restrict__ w3, const float* __restrict__ b3,
                              float* __restrict__ out_low) {
    extern __shared__ float sm[];
    ull*   w2p = (ull*)sm;                 // 576 entries = 4608 B
    float* ins = sm + 1152;                // 16 * 34 * 36 = 19584 floats
    float* b2s = ins + 19584;              // 8
    float* w3s = b2s + 8;                  // 32
    float* b3s = w3s + 32;                 // 4

    int img = blockIdx.z;
    int bx0 = blockIdx.x * 32, by0 = blockIdx.y * 32;   // conv2 origin (128x128)
    int tid = threadIdx.y * 16 + threadIdx.x;           // 256 threads

    // pack weights: (op, ic, k) -> (w2[2op][ic][k], w2[2op+1][ic][k])
    for (int i = tid; i < 576; i += 256) {
        int op = i / 144;
        int rem = i - op * 144;            // ic*9 + k
        w2p[i] = pack2(w2[(2 * op) * 144 + rem], w2[(2 * op + 1) * 144 + rem]);
    }
    if (tid < 8) b2s[tid] = b2[tid];
    if (tid < 32) w3s[tid] = w3[tid];
    if (tid < 4) b3s[tid] = b3[tid];

    const float* t1b = g_t1 + (size_t)img * 16 * 16384;
    for (int idx = tid; idx < 16 * 34 * 34; idx += 256) {
        int ic = idx / 1156;
        int rem = idx - ic * 1156;
        int r = rem / 34, c = rem - r * 34;
        int gy = by0 - 1 + r, gx = bx0 - 1 + c;
        float v = 0.f;
        if ((unsigned)gy < 128u && (unsigned)gx < 128u) v = t1b[ic * 16384 + gy * 128 + gx];
        ins[ic * 1224 + r * 36 + c] = v;
    }
    __syncthreads();

    int ly = 2 * threadIdx.y, lx = 2 * threadIdx.x;
    ull acc[4][4];
#pragma unroll
    for (int op = 0; op < 4; op++) {
        ull bb = pack2(b2s[2 * op], b2s[2 * op + 1]);
        acc[op][0] = bb; acc[op][1] = bb; acc[op][2] = bb; acc[op][3] = bb;
    }

#pragma unroll 1
    for (int ic = 0; ic < 16; ic++) {
        const float* ip = ins + ic * 1224 + ly * 36 + lx;
        float p[4][4];
#pragma unroll
        for (int r = 0; r < 4; r++) {
            float2 u0 = *(const float2*)(ip + r * 36);
            float2 u1 = *(const float2*)(ip + r * 36 + 2);
            p[r][0] = u0.x; p[r][1] = u0.y; p[r][2] = u1.x; p[r][3] = u1.y;
        }
        ull pd[4][4];
#pragma unroll
        for (int r = 0; r < 4; r++)
#pragma unroll
            for (int c = 0; c < 4; c++) pd[r][c] = dup2(p[r][c]);

#pragma unroll
        for (int op = 0; op < 4; op++) {
            const ull* wp = w2p + (op * 16 + ic) * 9;
#pragma unroll
            for (int ky = 0; ky < 3; ky++)
#pragma unroll
                for (int kx = 0; kx < 3; kx++) {
                    ull w = wp[ky * 3 + kx];
                    acc[op][0] = fma2(pd[ky][kx],         w, acc[op][0]);
                    acc[op][1] = fma2(pd[ky][kx + 1],     w, acc[op][1]);
                    acc[op][2] = fma2(pd[ky + 1][kx],     w, acc[op][2]);
                    acc[op][3] = fma2(pd[ky + 1][kx + 1], w, acc[op][3]);
                }
        }
    }

    float v8[8];
#pragma unroll
    for (int op = 0; op < 4; op++) {
        float s0l, s0h, s1l, s1h, s2l, s2h, s3l, s3h;
        unpack2(acc[op][0], s0l, s0h); unpack2(acc[op][1], s1l, s1h);
        unpack2(acc[op][2], s2l, s2h); unpack2(acc[op][3], s3l, s3h);
        float ml = fmaxf(fmaxf(s0l, s1l), fmaxf(s2l, s3l));
        float mh = fmaxf(fmaxf(s0h, s1h), fmaxf(s2h, s3h));
        v8[2 * op]     = fmaxf(ml, 0.f);
        v8[2 * op + 1] = fmaxf(mh, 0.f);
    }

    int oy = (by0 >> 1) + threadIdx.y;
    int ox = (bx0 >> 1) + threadIdx.x;
    float* ob = out_low + (size_t)img * 4 * 4096 + oy * 64 + ox;
#pragma unroll
    for (int o3 = 0; o3 < 4; o3++) {
        float s = b3s[o3];
#pragma unroll
        for (int ic = 0; ic < 8; ic++) s += v8[ic] * w3s[o3 * 8 + ic];
        ob[o3 * 4096] = s;
    }
}

// ---------------------------------------------------------------------------
extern "C" void kernel_launch(void* const* d_in, const int* in_sizes, int n_in,
                              void* d_out, int out_size) {
    const float* x  = (const float*)d_in[0];
    const float* w1 = (const float*)d_in[1];
    const float* b1 = (const float*)d_in[2];
    const float* w2 = (const float*)d_in[3];
    const float* b2 = (const float*)d_in[4];
    const float* w3 = (const float*)d_in[5];
    const float* b3 = (const float*)d_in[6];
    float* out = (float*)d_out;

    const int LOW_SIZE = 96 * 4 * 64 * 64;                    // 1,572,864
    const int SMEM_C = (1152 + 19584 + 8 + 32 + 4) * 4;       // 83,120 bytes

    cudaFuncSetAttribute(conv23_kernel, cudaFuncAttributeMaxDynamicSharedMemorySize, SMEM_C);

    dwt_kernel<<<dim3(128, 96), 256>>>(x, out + LOW_SIZE);
    conv1_kernel<<<dim3(8, 8, 96), dim3(16, 16)>>>(w1, b1);
    conv23_kernel<<<dim3(4, 4, 96), dim3(16, 16), SMEM_C>>>(w2, b2, w3, b3, out);
}

// round 4
// speedup vs baseline: 1.5153x; 1.3083x over previous
#include <cuda_runtime.h>

typedef unsigned long long ull;

// ---------------- packed f32x2 helpers (Blackwell FFMA2 path) ---------------
__device__ __forceinline__ ull pack2(float lo, float hi) {
    ull r; asm("mov.b64 %0, {%1, %2};" : "=l"(r) : "f"(lo), "f"(hi)); return r;
}
__device__ __forceinline__ ull dup2(float v) {
    ull r; asm("mov.b64 %0, {%1, %1};" : "=l"(r) : "f"(v)); return r;
}
__device__ __forceinline__ void unpack2(ull v, float& lo, float& hi) {
    asm("mov.b64 {%0, %1}, %2;" : "=f"(lo), "=f"(hi) : "l"(v));
}
__device__ __forceinline__ ull fma2(ull a, ull b, ull c) {
    ull d; asm("fma.rn.f32x2 %0, %1, %2, %3;" : "=l"(d) : "l"(a), "l"(b), "l"(c)); return d;
}

// ---------------- scratch (static device globals; no allocations) ----------
__device__ float g_cA[96 * 256 * 256];          // 25 MB

// ---------------- Kernel A: Haar DWT (float4 loads, 2 px / thread) ---------
__global__ void dwt_kernel(const float* __restrict__ x, float* __restrict__ out_high) {
    int img = blockIdx.y;
    int t = blockIdx.x * 256 + threadIdx.x;       // 0..32767
    int oy = t >> 7;
    int oxp = (t & 127) << 1;                     // even output col
    const float* base = x + (size_t)img * 262144 + (size_t)oy * 1024 + 2 * oxp;
    float4 tp = *(const float4*)base;
    float4 bt = *(const float4*)(base + 512);
    float cA0 = (tp.x + tp.y + bt.x + bt.y) * 0.5f;
    float cH0 = (tp.x + tp.y - bt.x - bt.y) * 0.5f;
    float cV0 = (tp.x - tp.y + bt.x - bt.y) * 0.5f;
    float cA1 = (tp.z + tp.w + bt.z + bt.w) * 0.5f;
    float cH1 = (tp.z + tp.w - bt.z - bt.w) * 0.5f;
    float cV1 = (tp.z - tp.w + bt.z - bt.w) * 0.5f;
    int o = oy * 256 + oxp;
    *(float2*)(g_cA + (size_t)img * 65536 + o) = make_float2(cA0, cA1);
    float* hb = out_high + (size_t)img * 131072;
    *(float2*)(hb + o) = make_float2(cH0, cH1);
    *(float2*)(hb + 65536 + o) = make_float2(cV0, cV1);
}

// ---------------- Fused kernel: conv1+relu+pool + conv2+relu+pool + conv3 ---
// grid (4,4,96), block 256. Each block -> 16x16 out_low tile.
// Phase 1: cA 70x70 halo tile -> t1 34x34x16 tile in smem (conv1 recompute in halo).
// Phase 2: conv2(16->8,3x3)+relu+pool+conv3(8->4,1x1) from smem t1.
__global__ void __launch_bounds__(256, 2)
fused_conv_kernel(const float* __restrict__ w1, const float* __restrict__ b1,
                  const float* __restrict__ w2, const float* __restrict__ b2,
                  const float* __restrict__ w3, const float* __restrict__ b3,
                  float* __restrict__ out_low) {
    extern __shared__ float sm[];
    float* cAt = sm;                       // 70 * 72 = 5040 floats
    float* ins = sm + 5040;                // 16 * 34 * 36 = 19584 floats
    ull*   w2p = (ull*)(ins + 19584);      // 576 ull = 1152 float slots
    ull*   w1p = w2p + 576;                // 72 ull = 144 float slots
    float* tail = (float*)(w1p + 72);
    float* b1s = tail;                     // 16
    float* b2s = tail + 16;                // 8
    float* w3s = tail + 24;                // 32
    float* b3s = tail + 56;                // 4

    int img = blockIdx.z;
    int bx0 = blockIdx.x * 32, by0 = blockIdx.y * 32;   // conv2 origin in 128x128
    int tid = threadIdx.x;                               // 256 threads

    // ---- weights ----
    if (tid < 72) {
        int op = tid / 9, k = tid - op * 9;
        w1p[tid] = pack2(w1[(2 * op) * 9 + k], w1[(2 * op + 1) * 9 + k]);
    }
    for (int i = tid; i < 576; i += 256) {
        int op = i / 144;
        int rem = i - op * 144;
        w2p[i] = pack2(w2[(2 * op) * 144 + rem], w2[(2 * op + 1) * 144 + rem]);
    }
    if (tid < 16) b1s[tid] = b1[tid];
    if (tid < 8) b2s[tid] = b2[tid];
    if (tid < 32) w3s[tid] = w3[tid];
    if (tid < 4) b3s[tid] = b3[tid];

    // ---- load cA halo tile: 70x70, origin (2*by0-3, 2*bx0-3) in 256x256 ----
    {
        const float* in = g_cA + (size_t)img * 65536;
        int cy0 = 2 * by0 - 3, cx0 = 2 * bx0 - 3;
        for (int idx = tid; idx < 70 * 70; idx += 256) {
            int r = idx / 70, c = idx - r * 70;
            int gy = cy0 + r, gx = cx0 + c;
            float v = 0.f;
            if ((unsigned)gy < 256u && (unsigned)gx < 256u) v = in[gy * 256 + gx];
            cAt[r * 72 + c] = v;
        }
    }
    __syncthreads();

    // ---- phase 1: t1 tile (34x34 positions x 16 ch) ----
    for (int pos = tid; pos < 34 * 34; pos += 256) {
        int r = pos / 34, c = pos - r * 34;
        int ty = by0 - 1 + r, tx = bx0 - 1 + c;       // global t1 coords
        if ((unsigned)ty < 128u && (unsigned)tx < 128u) {
            // patch: cA tile rows 2r..2r+3, cols 2c..2c+3 (8-byte aligned)
            const float* ip = cAt + 2 * r * 72 + 2 * c;
            ull pd[4][4];
#pragma unroll
            for (int rr = 0; rr < 4; rr++) {
                float2 u0 = *(const float2*)(ip + rr * 72);
                float2 u1 = *(const float2*)(ip + rr * 72 + 2);
                pd[rr][0] = dup2(u0.x); pd[rr][1] = dup2(u0.y);
                pd[rr][2] = dup2(u1.x); pd[rr][3] = dup2(u1.y);
            }
            float* op_out = ins + r * 36 + c;
#pragma unroll
            for (int op = 0; op < 8; op++) {
                ull bb = pack2(b1s[2 * op], b1s[2 * op + 1]);
                ull a0 = bb, a1 = bb, a2 = bb, a3 = bb;
                const ull* wp = w1p + op * 9;
#pragma unroll
                for (int ky = 0; ky < 3; ky++)
#pragma unroll
                    for (int kx = 0; kx < 3; kx++) {
                        ull w = wp[ky * 3 + kx];
                        a0 = fma2(pd[ky][kx],         w, a0);
                        a1 = fma2(pd[ky][kx + 1],     w, a1);
                        a2 = fma2(pd[ky + 1][kx],     w, a2);
                        a3 = fma2(pd[ky + 1][kx + 1], w, a3);
                    }
                float s0l, s0h, s1l, s1h, s2l, s2h, s3l, s3h;
                unpack2(a0, s0l, s0h); unpack2(a1, s1l, s1h);
                unpack2(a2, s2l, s2h); unpack2(a3, s3l, s3h);
                float ml = fmaxf(fmaxf(s0l, s1l), fmaxf(s2l, s3l));
                float mh = fmaxf(fmaxf(s0h, s1h), fmaxf(s2h, s3h));
                op_out[(2 * op) * 1224]     = fmaxf(ml, 0.f);
                op_out[(2 * op + 1) * 1224] = fmaxf(mh, 0.f);
            }
        } else {
            float* op_out = ins + r * 36 + c;
#pragma unroll
            for (int ic = 0; ic < 16; ic++) op_out[ic * 1224] = 0.f;
        }
    }
    __syncthreads();

    // ---- phase 2: conv2 + relu + pool + conv3 ----
    int tyx = tid & 15, tyy = tid >> 4;               // 16x16 thread layout
    int ly = 2 * tyy, lx = 2 * tyx;
    ull acc[4][4];
#pragma unroll
    for (int op = 0; op < 4; op++) {
        ull bb = pack2(b2s[2 * op], b2s[2 * op + 1]);
        acc[op][0] = bb; acc[op][1] = bb; acc[op][2] = bb; acc[op][3] = bb;
    }

#pragma unroll 1
    for (int ic = 0; ic < 16; ic++) {
        const float* ip = ins + ic * 1224 + ly * 36 + lx;
        ull pd[4][4];
#pragma unroll
        for (int rr = 0; rr < 4; rr++) {
            float2 u0 = *(const float2*)(ip + rr * 36);
            float2 u1 = *(const float2*)(ip + rr * 36 + 2);
            pd[rr][0] = dup2(u0.x); pd[rr][1] = dup2(u0.y);
            pd[rr][2] = dup2(u1.x); pd[rr][3] = dup2(u1.y);
        }
#pragma unroll
        for (int op = 0; op < 4; op++) {
            const ull* wp = w2p + (op * 16 + ic) * 9;
#pragma unroll
            for (int ky = 0; ky < 3; ky++)
#pragma unroll
                for (int kx = 0; kx < 3; kx++) {
                    ull w = wp[ky * 3 + kx];
                    acc[op][0] = fma2(pd[ky][kx],         w, acc[op][0]);
                    acc[op][1] = fma2(pd[ky][kx + 1],     w, acc[op][1]);
                    acc[op][2] = fma2(pd[ky + 1][kx],     w, acc[op][2]);
                    acc[op][3] = fma2(pd[ky + 1][kx + 1], w, acc[op][3]);
                }
        }
    }

    float v8[8];
#pragma unroll
    for (int op = 0; op < 4; op++) {
        float s0l, s0h, s1l, s1h, s2l, s2h, s3l, s3h;
        unpack2(acc[op][0], s0l, s0h); unpack2(acc[op][1], s1l, s1h);
        unpack2(acc[op][2], s2l, s2h); unpack2(acc[op][3], s3l, s3h);
        float ml = fmaxf(fmaxf(s0l, s1l), fmaxf(s2l, s3l));
        float mh = fmaxf(fmaxf(s0h, s1h), fmaxf(s2h, s3h));
        v8[2 * op]     = fmaxf(ml, 0.f);
        v8[2 * op + 1] = fmaxf(mh, 0.f);
    }

    int oy = (by0 >> 1) + tyy;
    int ox = (bx0 >> 1) + tyx;
    float* ob = out_low + (size_t)img * 4 * 4096 + oy * 64 + ox;
#pragma unroll
    for (int o3 = 0; o3 < 4; o3++) {
        float s = b3s[o3];
#pragma unroll
        for (int ic = 0; ic < 8; ic++) s += v8[ic] * w3s[o3 * 8 + ic];
        ob[o3 * 4096] = s;
    }
}

// ---------------------------------------------------------------------------
extern "C" void kernel_launch(void* const* d_in, const int* in_sizes, int n_in,
                              void* d_out, int out_size) {
    const float* x  = (const float*)d_in[0];
    const float* w1 = (const float*)d_in[1];
    const float* b1 = (const float*)d_in[2];
    const float* w2 = (const float*)d_in[3];
    const float* b2 = (const float*)d_in[4];
    const float* w3 = (const float*)d_in[5];
    const float* b3 = (const float*)d_in[6];
    float* out = (float*)d_out;

    const int LOW_SIZE = 96 * 4 * 64 * 64;                         // 1,572,864
    const int SMEM_F = (5040 + 19584 + 1152 + 144 + 60) * 4;       // 103,920 B

    cudaFuncSetAttribute(fused_conv_kernel, cudaFuncAttributeMaxDynamicSharedMemorySize, SMEM_F);

    dwt_kernel<<<dim3(128, 96), 256>>>(x, out + LOW_SIZE);
    fused_conv_kernel<<<dim3(4, 4, 96), 256, SMEM_F>>>(w1, b1, w2, b2, w3, b3, out);
}

// round 5
// speedup vs baseline: 1.5728x; 1.0379x over previous
#include <cuda_runtime.h>

typedef unsigned long long ull;

// ---------------- packed f32x2 helpers (Blackwell FFMA2 path) ---------------
__device__ __forceinline__ ull pack2(float lo, float hi) {
    ull r; asm("mov.b64 %0, {%1, %2};" : "=l"(r) : "f"(lo), "f"(hi)); return r;
}
__device__ __forceinline__ ull dup2(float v) {
    ull r; asm("mov.b64 %0, {%1, %1};" : "=l"(r) : "f"(v)); return r;
}
__device__ __forceinline__ void unpack2(ull v, float& lo, float& hi) {
    asm("mov.b64 {%0, %1}, %2;" : "=f"(lo), "=f"(hi) : "l"(v));
}
__device__ __forceinline__ ull fma2(ull a, ull b, ull c) {
    ull d; asm("fma.rn.f32x2 %0, %1, %2, %3;" : "=l"(d) : "l"(a), "l"(b), "l"(c)); return d;
}

// ---------------- scratch (static device globals; no allocations) ----------
__device__ float g_cA[96 * 256 * 256];          // 25 MB

// ---------------- Kernel A: Haar DWT (float4 loads, 2 px / thread) ---------
__global__ void dwt_kernel(const float* __restrict__ x, float* __restrict__ out_high) {
    int img = blockIdx.y;
    int t = blockIdx.x * 256 + threadIdx.x;       // 0..32767
    int oy = t >> 7;
    int oxp = (t & 127) << 1;                     // even output col
    const float* base = x + (size_t)img * 262144 + (size_t)oy * 1024 + 2 * oxp;
    float4 tp = *(const float4*)base;
    float4 bt = *(const float4*)(base + 512);
    float cA0 = (tp.x + tp.y + bt.x + bt.y) * 0.5f;
    float cH0 = (tp.x + tp.y - bt.x - bt.y) * 0.5f;
    float cV0 = (tp.x - tp.y + bt.x - bt.y) * 0.5f;
    float cA1 = (tp.z + tp.w + bt.z + bt.w) * 0.5f;
    float cH1 = (tp.z + tp.w - bt.z - bt.w) * 0.5f;
    float cV1 = (tp.z - tp.w + bt.z - bt.w) * 0.5f;
    int o = oy * 256 + oxp;
    *(float2*)(g_cA + (size_t)img * 65536 + o) = make_float2(cA0, cA1);
    float* hb = out_high + (size_t)img * 131072;
    *(float2*)(hb + o) = make_float2(cH0, cH1);
    *(float2*)(hb + 65536 + o) = make_float2(cV0, cV1);
}

// 9-tap accumulate macro: packed weight W applied to 2x2 conv positions
#define K9(W, KY, KX)                                   \
    a0 = fma2(pd[(KY)][(KX)],         (W), a0);         \
    a1 = fma2(pd[(KY)][(KX) + 1],     (W), a1);         \
    a2 = fma2(pd[(KY) + 1][(KX)],     (W), a2);         \
    a3 = fma2(pd[(KY) + 1][(KX) + 1], (W), a3);

// ---------------- Fused kernel: conv1+relu+pool + conv2+relu+pool + conv3 ---
// grid (4,4,96), block 512 (32 warps/SM at 2 blocks). 16x16 out_low tile/block.
__global__ void __launch_bounds__(512, 2)
fused_conv_kernel(const float* __restrict__ w1, const float* __restrict__ b1,
                  const float* __restrict__ w2, const float* __restrict__ b2,
                  const float* __restrict__ w3, const float* __restrict__ b3,
                  float* __restrict__ out_low) {
    extern __shared__ float sm[];
    float* cAt = sm;                       // 70 * 72 = 5040 floats
    float* ins = sm + 5040;                // 16 * 34 * 36 = 19584 floats
    ull*   w2p = (ull*)(ins + 19584);      // 4 op * 16 ic * 10 = 640 ull (1280 fl)
    ull*   w1p = w2p + 640;                // 8 op * 10 = 80 ull (160 fl)
    float* tail = (float*)(w1p + 80);
    float* b1s = tail;                     // 16
    float* b2s = tail + 16;                // 8
    float* w3s = tail + 24;                // 32
    float* b3s = tail + 56;                // 4
    float* v4buf = tail + 64;              // 256 * 8 = 2048 floats

    int img = blockIdx.z;
    int bx0 = blockIdx.x * 32, by0 = blockIdx.y * 32;   // conv2 origin in 128x128
    int tid = threadIdx.x;                               // 512 threads

    // ---- weights (padded k: 10 per (op,ic) for LDS.128 pairs) ----
    if (tid < 80) {
        int op = tid / 10, k = tid - op * 10;
        w1p[tid] = (k < 9) ? pack2(w1[(2 * op) * 9 + k], w1[(2 * op + 1) * 9 + k]) : 0ull;
    }
    for (int i = tid; i < 640; i += 512) {
        int op = i / 160;
        int rem = i - op * 160;            // ic*10 + k
        int ic = rem / 10, k = rem - ic * 10;
        w2p[i] = (k < 9) ? pack2(w2[(2 * op) * 144 + ic * 9 + k],
                                 w2[(2 * op + 1) * 144 + ic * 9 + k]) : 0ull;
    }
    if (tid < 16) b1s[tid] = b1[tid];
    if (tid < 8) b2s[tid] = b2[tid];
    if (tid < 32) w3s[tid] = w3[tid];
    if (tid < 4) b3s[tid] = b3[tid];

    // ---- load cA halo tile: 70x70, origin (2*by0-3, 2*bx0-3) in 256x256 ----
    {
        const float* in = g_cA + (size_t)img * 65536;
        int cy0 = 2 * by0 - 3, cx0 = 2 * bx0 - 3;
        for (int idx = tid; idx < 70 * 70; idx += 512) {
            int r = idx / 70, c = idx - r * 70;
            int gy = cy0 + r, gx = cx0 + c;
            float v = 0.f;
            if ((unsigned)gy < 256u && (unsigned)gx < 256u) v = in[gy * 256 + gx];
            cAt[r * 72 + c] = v;
        }
    }
    __syncthreads();

    // ---- phase 1: t1 tile (34x34 positions x 16 ch) ----
    for (int pos = tid; pos < 34 * 34; pos += 512) {
        int r = pos / 34, c = pos - r * 34;
        int ty = by0 - 1 + r, tx = bx0 - 1 + c;       // global t1 coords
        float* op_out = ins + r * 36 + c;
        if ((unsigned)ty < 128u && (unsigned)tx < 128u) {
            const float* ip = cAt + 2 * r * 72 + 2 * c;
            ull pd[4][4];
#pragma unroll
            for (int rr = 0; rr < 4; rr++) {
                float2 u0 = *(const float2*)(ip + rr * 72);
                float2 u1 = *(const float2*)(ip + rr * 72 + 2);
                pd[rr][0] = dup2(u0.x); pd[rr][1] = dup2(u0.y);
                pd[rr][2] = dup2(u1.x); pd[rr][3] = dup2(u1.y);
            }
#pragma unroll
            for (int op = 0; op < 8; op++) {
                ull bb = pack2(b1s[2 * op], b1s[2 * op + 1]);
                ull a0 = bb, a1 = bb, a2 = bb, a3 = bb;
                const ull* wp = w1p + op * 10;
                ulonglong2 w01 = *(const ulonglong2*)wp;
                ulonglong2 w23 = *(const ulonglong2*)(wp + 2);
                ulonglong2 w45 = *(const ulonglong2*)(wp + 4);
                ulonglong2 w67 = *(const ulonglong2*)(wp + 6);
                ull w8 = wp[8];
                K9(w01.x, 0, 0) K9(w01.y, 0, 1) K9(w23.x, 0, 2)
                K9(w23.y, 1, 0) K9(w45.x, 1, 1) K9(w45.y, 1, 2)
                K9(w67.x, 2, 0) K9(w67.y, 2, 1) K9(w8,    2, 2)
                float s0l, s0h, s1l, s1h, s2l, s2h, s3l, s3h;
                unpack2(a0, s0l, s0h); unpack2(a1, s1l, s1h);
                unpack2(a2, s2l, s2h); unpack2(a3, s3l, s3h);
                float ml = fmaxf(fmaxf(s0l, s1l), fmaxf(s2l, s3l));
                float mh = fmaxf(fmaxf(s0h, s1h), fmaxf(s2h, s3h));
                op_out[(2 * op) * 1224]     = fmaxf(ml, 0.f);
                op_out[(2 * op + 1) * 1224] = fmaxf(mh, 0.f);
            }
        } else {
#pragma unroll
            for (int ic = 0; ic < 16; ic++) op_out[ic * 1224] = 0.f;
        }
    }
    __syncthreads();

    // ---- phase 2: conv2 + relu + pool (oc split across 2 thread groups) ----
    int pix = tid & 255, g = tid >> 8;                // g: op-pairs {2g, 2g+1}
    int tyx = pix & 15, tyy = pix >> 4;
    int ly = 2 * tyy, lx = 2 * tyx;
    ull acc[2][4];
#pragma unroll
    for (int op2 = 0; op2 < 2; op2++) {
        int op = 2 * g + op2;
        ull bb = pack2(b2s[2 * op], b2s[2 * op + 1]);
        acc[op2][0] = bb; acc[op2][1] = bb; acc[op2][2] = bb; acc[op2][3] = bb;
    }

#pragma unroll 1
    for (int ic = 0; ic < 16; ic++) {
        const float* ip = ins + ic * 1224 + ly * 36 + lx;
        ull pd[4][4];
#pragma unroll
        for (int rr = 0; rr < 4; rr++) {
            float2 u0 = *(const float2*)(ip + rr * 36);
            float2 u1 = *(const float2*)(ip + rr * 36 + 2);
            pd[rr][0] = dup2(u0.x); pd[rr][1] = dup2(u0.y);
            pd[rr][2] = dup2(u1.x); pd[rr][3] = dup2(u1.y);
        }
#pragma unroll
        for (int op2 = 0; op2 < 2; op2++) {
            int op = 2 * g + op2;
            const ull* wp = w2p + (op * 16 + ic) * 10;
            ulonglong2 w01 = *(const ulonglong2*)wp;
            ulonglong2 w23 = *(const ulonglong2*)(wp + 2);
            ulonglong2 w45 = *(const ulonglong2*)(wp + 4);
            ulonglong2 w67 = *(const ulonglong2*)(wp + 6);
            ull w8 = wp[8];
            ull a0 = acc[op2][0], a1 = acc[op2][1], a2 = acc[op2][2], a3 = acc[op2][3];
            K9(w01.x, 0, 0) K9(w01.y, 0, 1) K9(w23.x, 0, 2)
            K9(w23.y, 1, 0) K9(w45.x, 1, 1) K9(w45.y, 1, 2)
            K9(w67.x, 2, 0) K9(w67.y, 2, 1) K9(w8,    2, 2)
            acc[op2][0] = a0; acc[op2][1] = a1; acc[op2][2] = a2; acc[op2][3] = a3;
        }
    }

    float v4[4];
#pragma unroll
    for (int op2 = 0; op2 < 2; op2++) {
        float s0l, s0h, s1l, s1h, s2l, s2h, s3l, s3h;
        unpack2(acc[op2][0], s0l, s0h); unpack2(acc[op2][1], s1l, s1h);
        unpack2(acc[op2][2], s2l, s2h); unpack2(acc[op2][3], s3l, s3h);
        float ml = fmaxf(fmaxf(s0l, s1l), fmaxf(s2l, s3l));
        float mh = fmaxf(fmaxf(s0h, s1h), fmaxf(s2h, s3h));
        v4[2 * op2]     = fmaxf(ml, 0.f);
        v4[2 * op2 + 1] = fmaxf(mh, 0.f);
    }
    *(float4*)(v4buf + pix * 8 + 4 * g) = make_float4(v4[0], v4[1], v4[2], v4[3]);
    __syncthreads();

    // ---- conv3 (8->4, 1x1) from exchanged v8 ----
    if (tid < 256) {
        float4 lo4 = *(const float4*)(v4buf + tid * 8);
        float4 hi4 = *(const float4*)(v4buf + tid * 8 + 4);
        float v8[8] = {lo4.x, lo4.y, lo4.z, lo4.w, hi4.x, hi4.y, hi4.z, hi4.w};
        int oy = (by0 >> 1) + (tid >> 4);
        int ox = (bx0 >> 1) + (tid & 15);
        float* ob = out_low + (size_t)img * 4 * 4096 + oy * 64 + ox;
#pragma unroll
        for (int o3 = 0; o3 < 4; o3++) {
            float s = b3s[o3];
#pragma unroll
            for (int ic = 0; ic < 8; ic++) s += v8[ic] * w3s[o3 * 8 + ic];
            ob[o3 * 4096] = s;
        }
    }
}

// ---------------------------------------------------------------------------
extern "C" void kernel_launch(void* const* d_in, const int* in_sizes, int n_in,
                              void* d_out, int out_size) {
    const float* x  = (const float*)d_in[0];
    const float* w1 = (const float*)d_in[1];
    const float* b1 = (const float*)d_in[2];
    const float* w2 = (const float*)d_in[3];
    const float* b2 = (const float*)d_in[4];
    const float* w3 = (const float*)d_in[5];
    const float* b3 = (const float*)d_in[6];
    float* out = (float*)d_out;

    const int LOW_SIZE = 96 * 4 * 64 * 64;                               // 1,572,864
    const int SMEM_F = (5040 + 19584 + 1280 + 160 + 64 + 2048) * 4;      // 112,704 B

    cudaFuncSetAttribute(fused_conv_kernel, cudaFuncAttributeMaxDynamicSharedMemorySize, SMEM_F);

    dwt_kernel<<<dim3(128, 96), 256>>>(x, out + LOW_SIZE);
    fused_conv_kernel<<<dim3(4, 4, 96), 512, SMEM_F>>>(w1, b1, w2, b2, w3, b3, out);
}

// round 7
// speedup vs baseline: 1.7005x; 1.0812x over previous
#include <cuda_runtime.h>
#include <cstdint>

typedef unsigned long long ull;

// ---------------- packed f32x2 helpers (Blackwell FFMA2 path) ---------------
__device__ __forceinline__ ull pack2(float lo, float hi) {
    ull r; asm("mov.b64 %0, {%1, %2};" : "=l"(r) : "f"(lo), "f"(hi)); return r;
}
__device__ __forceinline__ ull dup2(float v) {
    ull r; asm("mov.b64 %0, {%1, %1};" : "=l"(r) : "f"(v)); return r;
}
__device__ __forceinline__ void unpack2(ull v, float& lo, float& hi) {
    asm("mov.b64 {%0, %1}, %2;" : "=f"(lo), "=f"(hi) : "l"(v));
}
__device__ __forceinline__ ull fma2(ull a, ull b, ull c) {
    ull d; asm("fma.rn.f32x2 %0, %1, %2, %3;" : "=l"(d) : "l"(a), "l"(b), "l"(c)); return d;
}
__device__ __forceinline__ void cp_async4(unsigned int saddr, const void* gptr, int src_sz) {
    asm volatile("cp.async.ca.shared.global [%0], [%1], 4, %2;"
                 :: "r"(saddr), "l"(gptr), "r"(src_sz));
}
__device__ __forceinline__ void cp_commit() { asm volatile("cp.async.commit_group;"); }
__device__ __forceinline__ void cp_wait0()  { asm volatile("cp.async.wait_group 0;"); }

// ---------------- scratch (static device globals; no allocations) ----------
__device__ float g_cA[96 * 256 * 256];          // 25 MB

// ---------------- Kernel A: Haar DWT (float4 loads, 2 px / thread) ---------
__global__ void dwt_kernel(const float* __restrict__ x, float* __restrict__ out_high) {
    int img = blockIdx.y;
    int t = blockIdx.x * 256 + threadIdx.x;       // 0..32767
    int oy = t >> 7;
    int oxp = (t & 127) << 1;                     // even output col
    const float* base = x + (size_t)img * 262144 + (size_t)oy * 1024 + 2 * oxp;
    float4 tp = *(const float4*)base;
    float4 bt = *(const float4*)(base + 512);
    float cA0 = (tp.x + tp.y + bt.x + bt.y) * 0.5f;
    float cH0 = (tp.x + tp.y - bt.x - bt.y) * 0.5f;
    float cV0 = (tp.x - tp.y + bt.x - bt.y) * 0.5f;
    float cA1 = (tp.z + tp.w + bt.z + bt.w) * 0.5f;
    float cH1 = (tp.z + tp.w - bt.z - bt.w) * 0.5f;
    float cV1 = (tp.z - tp.w + bt.z - bt.w) * 0.5f;
    int o = oy * 256 + oxp;
    *(float2*)(g_cA + (size_t)img * 65536 + o) = make_float2(cA0, cA1);
    float* hb = out_high + (size_t)img * 131072;
    *(float2*)(hb + o) = make_float2(cH0, cH1);
    *(float2*)(hb + 65536 + o) = make_float2(cV0, cV1);
}

// 9-tap accumulate macro: packed weight W applied to 2x2 conv positions
#define K9(W, KY, KX)                                   \
    a0 = fma2(pd[(KY)][(KX)],         (W), a0);         \
    a1 = fma2(pd[(KY)][(KX) + 1],     (W), a1);         \
    a2 = fma2(pd[(KY) + 1][(KX)],     (W), a2);         \
    a3 = fma2(pd[(KY) + 1][(KX) + 1], (W), a3);

#define NBLK 296
#define NTILE 1536

// ---------------- Persistent fused kernel -----------------------------------
// grid 296 (2/SM), block 512. Each block loops tiles bid, bid+296, ...
// Per tile: phase1 conv1+pool -> smem t1; phase2 conv2+pool; conv3.
// cA tile for next iteration prefetched via cp.async during phase 2.
__global__ void __launch_bounds__(512, 2)
fused_conv_kernel(const float* __restrict__ w1, const float* __restrict__ b1,
                  const float* __restrict__ w2, const float* __restrict__ b2,
                  const float* __restrict__ w3, const float* __restrict__ b3,
                  float* __restrict__ out_low) {
    extern __shared__ float sm[];
    float* cAt = sm;                       // 70 * 72 = 5040 floats
    float* ins = sm + 5040;                // 16 * 34 * 36 = 19584 floats
    ull*   w2p = (ull*)(ins + 19584);      // 640 ull
    ull*   w1p = w2p + 640;                // 80 ull
    float* tail = (float*)(w1p + 80);
    float* b1s = tail;                     // 16
    float* b2s = tail + 16;                // 8
    float* w3s = tail + 24;                // 32
    float* b3s = tail + 56;                // 4
    float* v4buf = tail + 64;              // 2048 floats

    int tid = threadIdx.x;                               // 512 threads

    // ---- weights (once per block) ----
    if (tid < 80) {
        int op = tid / 10, k = tid - op * 10;
        w1p[tid] = (k < 9) ? pack2(w1[(2 * op) * 9 + k], w1[(2 * op + 1) * 9 + k]) : 0ull;
    }
    for (int i = tid; i < 640; i += 512) {
        int op = i / 160;
        int rem = i - op * 160;            // ic*10 + k
        int ic = rem / 10, k = rem - ic * 10;
        w2p[i] = (k < 9) ? pack2(w2[(2 * op) * 144 + ic * 9 + k],
                                 w2[(2 * op + 1) * 144 + ic * 9 + k]) : 0ull;
    }
    if (tid < 16) b1s[tid] = b1[tid];
    if (tid < 8) b2s[tid] = b2[tid];
    if (tid < 32) w3s[tid] = w3[tid];
    if (tid < 4) b3s[tid] = b3[tid];

    unsigned int cAt_s = (unsigned int)__cvta_generic_to_shared(cAt);

    // initial prefetch for first tile
    {
        int tile0 = blockIdx.x;
        int img = tile0 >> 4;
        int tt = tile0 & 15;
        int by0 = (tt >> 2) * 32, bx0 = (tt & 3) * 32;
        const float* in = g_cA + (size_t)img * 65536;
        int cy0 = 2 * by0 - 3, cx0 = 2 * bx0 - 3;
        for (int idx = tid; idx < 70 * 70; idx += 512) {
            int r = idx / 70, c = idx - r * 70;
            int gy = cy0 + r, gx = cx0 + c;
            bool ok = ((unsigned)gy < 256u) && ((unsigned)gx < 256u);
            const float* src = ok ? (in + gy * 256 + gx) : in;
            cp_async4(cAt_s + (unsigned int)(r * 72 + c) * 4u, src, ok ? 4 : 0);
        }
        cp_commit();
    }

    for (int tile = blockIdx.x; tile < NTILE; tile += NBLK) {
        int img = tile >> 4;
        int tt = tile & 15;
        int by0 = (tt >> 2) * 32, bx0 = (tt & 3) * 32;

        cp_wait0();
        __syncthreads();                   // cAt ready, prior-tile v4buf free

        // ---- phase 1: t1 tile (34x34 positions x 16 ch) ----
        for (int pos = tid; pos < 34 * 34; pos += 512) {
            int r = pos / 34, c = pos - r * 34;
            int ty = by0 - 1 + r, tx = bx0 - 1 + c;       // global t1 coords
            float* op_out = ins + r * 36 + c;
            if ((unsigned)ty < 128u && (unsigned)tx < 128u) {
                const float* ip = cAt + 2 * r * 72 + 2 * c;
                ull pd[4][4];
#pragma unroll
                for (int rr = 0; rr < 4; rr++) {
                    float2 u0 = *(const float2*)(ip + rr * 72);
                    float2 u1 = *(const float2*)(ip + rr * 72 + 2);
                    pd[rr][0] = dup2(u0.x); pd[rr][1] = dup2(u0.y);
                    pd[rr][2] = dup2(u1.x); pd[rr][3] = dup2(u1.y);
                }
#pragma unroll
                for (int op = 0; op < 8; op++) {
                    ull bb = pack2(b1s[2 * op], b1s[2 * op + 1]);
                    ull a0 = bb, a1 = bb, a2 = bb, a3 = bb;
                    const ull* wp = w1p + op * 10;
                    ulonglong2 w01 = *(const ulonglong2*)wp;
                    ulonglong2 w23 = *(const ulonglong2*)(wp + 2);
                    ulonglong2 w45 = *(const ulonglong2*)(wp + 4);
                    ulonglong2 w67 = *(const ulonglong2*)(wp + 6);
                    ull w8 = wp[8];
                    K9(w01.x, 0, 0) K9(w01.y, 0, 1) K9(w23.x, 0, 2)
                    K9(w23.y, 1, 0) K9(w45.x, 1, 1) K9(w45.y, 1, 2)
                    K9(w67.x, 2, 0) K9(w67.y, 2, 1) K9(w8,    2, 2)
                    float s0l, s0h, s1l, s1h, s2l, s2h, s3l, s3h;
                    unpack2(a0, s0l, s0h); unpack2(a1, s1l, s1h);
                    unpack2(a2, s2l, s2h); unpack2(a3, s3l, s3h);
                    float ml = fmaxf(fmaxf(s0l, s1l), fmaxf(s2l, s3l));
                    float mh = fmaxf(fmaxf(s0h, s1h), fmaxf(s2h, s3h));
                    op_out[(2 * op) * 1224]     = fmaxf(ml, 0.f);
                    op_out[(2 * op + 1) * 1224] = fmaxf(mh, 0.f);
                }
            } else {
#pragma unroll
                for (int ic = 0; ic < 16; ic++) op_out[ic * 1224] = 0.f;
            }
        }
        __syncthreads();                   // ins ready, cAt dead

        // ---- prefetch next tile's cA halo into cAt (overlaps phase 2) ----
        {
            int nt = tile + NBLK;
            if (nt < NTILE) {
                int nimg = nt >> 4;
                int ntt = nt & 15;
                int nby = (ntt >> 2) * 32, nbx = (ntt & 3) * 32;
                const float* nin = g_cA + (size_t)nimg * 65536;
                int cy0 = 2 * nby - 3, cx0 = 2 * nbx - 3;
                for (int idx = tid; idx < 70 * 70; idx += 512) {
                    int r = idx / 70, c = idx - r * 70;
                    int gy = cy0 + r, gx = cx0 + c;
                    bool ok = ((unsigned)gy < 256u) && ((unsigned)gx < 256u);
                    const float* src = ok ? (nin + gy * 256 + gx) : nin;
                    cp_async4(cAt_s + (unsigned int)(r * 72 + c) * 4u, src, ok ? 4 : 0);
                }
            }
            cp_commit();
        }

        // ---- phase 2: conv2 + relu + pool (oc split across 2 groups) ----
        int pix = tid & 255, g = tid >> 8;
        int tyx = pix & 15, tyy = pix >> 4;
        int ly = 2 * tyy, lx = 2 * tyx;
        ull acc[2][4];
#pragma unroll
        for (int op2 = 0; op2 < 2; op2++) {
            int op = 2 * g + op2;
            ull bb = pack2(b2s[2 * op], b2s[2 * op + 1]);
            acc[op2][0] = bb; acc[op2][1] = bb; acc[op2][2] = bb; acc[op2][3] = bb;
        }

#pragma unroll 1
        for (int ic = 0; ic < 16; ic++) {
            const float* ip = ins + ic * 1224 + ly * 36 + lx;
            ull pd[4][4];
#pragma unroll
            for (int rr = 0; rr < 4; rr++) {
                float2 u0 = *(const float2*)(ip + rr * 36);
                float2 u1 = *(const float2*)(ip + rr * 36 + 2);
                pd[rr][0] = dup2(u0.x); pd[rr][1] = dup2(u0.y);
                pd[rr][2] = dup2(u1.x); pd[rr][3] = dup2(u1.y);
            }
#pragma unroll
            for (int op2 = 0; op2 < 2; op2++) {
                int op = 2 * g + op2;
                const ull* wp = w2p + (op * 16 + ic) * 10;
                ulonglong2 w01 = *(const ulonglong2*)wp;
                ulonglong2 w23 = *(const ulonglong2*)(wp + 2);
                ulonglong2 w45 = *(const ulonglong2*)(wp + 4);
                ulonglong2 w67 = *(const ulonglong2*)(wp + 6);
                ull w8 = wp[8];
                ull a0 = acc[op2][0], a1 = acc[op2][1], a2 = acc[op2][2], a3 = acc[op2][3];
                K9(w01.x, 0, 0) K9(w01.y, 0, 1) K9(w23.x, 0, 2)
                K9(w23.y, 1, 0) K9(w45.x, 1, 1) K9(w45.y, 1, 2)
                K9(w67.x, 2, 0) K9(w67.y, 2, 1) K9(w8,    2, 2)
                acc[op2][0] = a0; acc[op2][1] = a1; acc[op2][2] = a2; acc[op2][3] = a3;
            }
        }

        float v4[4];
#pragma unroll
        for (int op2 = 0; op2 < 2; op2++) {
            float s0l, s0h, s1l, s1h, s2l, s2h, s3l, s3h;
            unpack2(acc[op2][0], s0l, s0h); unpack2(acc[op2][1], s1l, s1h);
            unpack2(acc[op2][2], s2l, s2h); unpack2(acc[op2][3], s3l, s3h);
            float ml = fmaxf(fmaxf(s0l, s1l), fmaxf(s2l, s3l));
            float mh = fmaxf(fmaxf(s0h, s1h), fmaxf(s2h, s3h));
            v4[2 * op2]     = fmaxf(ml, 0.f);
            v4[2 * op2 + 1] = fmaxf(mh, 0.f);
        }
        *(float4*)(v4buf + pix * 8 + 4 * g) = make_float4(v4[0], v4[1], v4[2], v4[3]);
        __syncthreads();

        // ---- conv3 (8->4, 1x1): 512 threads, 2 outputs each ----
        {
            int p = tid >> 1;                    // pixel 0..255
            int half = (tid & 1) * 2;            // o3 in {half, half+1}
            float4 lo4 = *(const float4*)(v4buf + p * 8);
            float4 hi4 = *(const float4*)(v4buf + p * 8 + 4);
            float v8[8] = {lo4.x, lo4.y, lo4.z, lo4.w, hi4.x, hi4.y, hi4.z, hi4.w};
            int oy = (by0 >> 1) + (p >> 4);
            int ox = (bx0 >> 1) + (p & 15);
            float* ob = out_low + (size_t)img * 4 * 4096 + oy * 64 + ox;
#pragma unroll
            for (int j = 0; j < 2; j++) {
                int o3 = half + j;
                float s = b3s[o3];
#pragma unroll
                for (int ic = 0; ic < 8; ic++) s += v8[ic] * w3s[o3 * 8 + ic];
                ob[o3 * 4096] = s;
            }
        }
        // loop top: cp_wait0 + syncthreads orders cAt prefetch & v4buf reuse
    }
}

// ---------------------------------------------------------------------------
extern "C" void kernel_launch(void* const* d_in, const int* in_sizes, int n_in,
                              void* d_out, int out_size) {
    const float* x  = (const float*)d_in[0];
    const float* w1 = (const float*)d_in[1];
    const float* b1 = (const float*)d_in[2];
    const float* w2 = (const float*)d_in[3];
    const float* b2 = (const float*)d_in[4];
    const float* w3 = (const float*)d_in[5];
    const float* b3 = (const float*)d_in[6];
    float* out = (float*)d_out;

    const int LOW_SIZE = 96 * 4 * 64 * 64;                               // 1,572,864
    const int SMEM_F = (5040 + 19584 + 1280 + 160 + 64 + 2048) * 4;      // 112,704 B

    cudaFuncSetAttribute(fused_conv_kernel, cudaFuncAttributeMaxDynamicSharedMemorySize, SMEM_F);

    dwt_kernel<<<dim3(128, 96), 256>>>(x, out + LOW_SIZE);
    fused_conv_kernel<<<NBLK, 512, SMEM_F>>>(w1, b1, w2, b2, w3, b3, out);
}